// round 2
// baseline (speedup 1.0000x reference)
#include <cuda_runtime.h>
#include <cstddef>

#define KG   256      // gaussians
#define DF   12       // latent dim
#define CO   9        // sh channels
#define HH   32       // hidden
#define EPSF 1e-8f

#define TPB   256
#define NWARP 8
#define TLD   33      // padded tile leading dim (bank-conflict free transpose)

// shared memory layout (in floats)
#define OFF_G   0                       // KG*12: negmu0,negmu1,negmu2,Pf00 | Pf11,Pf22,Pf01x2,Pf02x2 | Pf12x2,r2,0,0
#define OFF_F   (KG * 12)               // KG*12: F[k][0..11]
#define OFF_W1  (KG * 24)               // 15*32
#define OFF_B1  (OFF_W1 + 15 * HH)      // 32
#define OFF_W2  (OFF_B1 + HH)           // 32*9
#define OFF_B2  (OFF_W2 + HH * CO)      // 9
#define OFF_T   (OFF_B2 + CO + 3)       // warp transpose tiles
#define SMEM_FLOATS (OFF_T + NWARP * 32 * TLD)
#define SMEM_BYTES  (SMEM_FLOATS * 4)

// gv = exp(-0.5 * d^T P d) * (dist^2 < r^2), with -0.5*log2(e) folded into P -> single EX2
__device__ __forceinline__ float gauss_eval(float px, float py, float pz,
                                            float4 g0, float4 g1, float4 g2) {
    float d0 = px + g0.x;
    float d1 = py + g0.y;
    float d2 = pz + g0.z;
    float a = d0 * d0;
    float b = d1 * d1;
    float c = d2 * d2;
    float dist2 = a + b + c;
    float m = a * g0.w;
    m = fmaf(b, g1.x, m);
    m = fmaf(c, g1.y, m);
    m = fmaf(d0 * d1, g1.z, m);
    m = fmaf(d0 * d2, g1.w, m);
    m = fmaf(d1 * d2, g2.x, m);
    float e;
    asm("ex2.approx.ftz.f32 %0, %1;" : "=f"(e) : "f"(m));
    return (dist2 < g2.y) ? e : 0.0f;
}

__global__ __launch_bounds__(TPB)
void gpc_kernel(const float* __restrict__ pos,
                const float* __restrict__ mu,
                const float* __restrict__ log_s,
                const float* __restrict__ q,
                const float* __restrict__ F,
                const float* __restrict__ W1,
                const float* __restrict__ b1,
                const float* __restrict__ W2,
                const float* __restrict__ b2,
                float* __restrict__ out_sh,
                float* __restrict__ out_lat,
                float* __restrict__ out_w,
                int N) {
    extern __shared__ float sm[];
    float* sG  = sm + OFF_G;
    float* sF  = sm + OFF_F;
    float* sW1 = sm + OFF_W1;
    float* sB1 = sm + OFF_B1;
    float* sW2 = sm + OFF_W2;
    float* sB2 = sm + OFF_B2;
    float* sT  = sm + OFF_T;

    const int tid = threadIdx.x;

    // ---------------- per-block setup: one gaussian per thread ----------------
    {
        const int k = tid;
        float m0 = mu[k * 3 + 0], m1 = mu[k * 3 + 1], m2 = mu[k * 3 + 2];

        float s0 = expf(log_s[k * 3 + 0]);
        float s1 = expf(log_s[k * 3 + 1]);
        float s2 = expf(log_s[k * 3 + 2]);
        float si0 = 1.0f / (s0 * s0 + EPSF);
        float si1 = 1.0f / (s1 * s1 + EPSF);
        float si2 = 1.0f / (s2 * s2 + EPSF);

        float qw = q[k * 4 + 0], qx = q[k * 4 + 1], qy = q[k * 4 + 2], qz = q[k * 4 + 3];
        float qn = sqrtf(qw * qw + qx * qx + qy * qy + qz * qz) + EPSF;
        qw /= qn; qx /= qn; qy /= qn; qz /= qn;

        float r00 = 1.0f - 2.0f * (qy * qy + qz * qz);
        float r01 = 2.0f * (qx * qy - qw * qz);
        float r02 = 2.0f * (qx * qz + qw * qy);
        float r10 = 2.0f * (qx * qy + qw * qz);
        float r11 = 1.0f - 2.0f * (qx * qx + qz * qz);
        float r12 = 2.0f * (qy * qz - qw * qx);
        float r20 = 2.0f * (qx * qz - qw * qy);
        float r21 = 2.0f * (qy * qz + qw * qx);
        float r22 = 1.0f - 2.0f * (qx * qx + qy * qy);

        // P = R diag(si) R^T (symmetric)
        float P00 = si0 * r00 * r00 + si1 * r01 * r01 + si2 * r02 * r02;
        float P11 = si0 * r10 * r10 + si1 * r11 * r11 + si2 * r12 * r12;
        float P22 = si0 * r20 * r20 + si1 * r21 * r21 + si2 * r22 * r22;
        float P01 = si0 * r00 * r10 + si1 * r01 * r11 + si2 * r02 * r12;
        float P02 = si0 * r00 * r20 + si1 * r01 * r21 + si2 * r02 * r22;
        float P12 = si0 * r10 * r20 + si1 * r11 * r21 + si2 * r12 * r22;

        const float cc = -0.72134752044448170f;  // -0.5 * log2(e)
        float smax = fmaxf(s0, fmaxf(s1, s2));
        float rad = 3.0f * smax;

        float* g = sG + k * 12;
        g[0] = -m0; g[1] = -m1; g[2] = -m2;
        g[3] = cc * P00;
        g[4] = cc * P11;
        g[5] = cc * P22;
        g[6] = 2.0f * cc * P01;
        g[7] = 2.0f * cc * P02;
        g[8] = 2.0f * cc * P12;
        g[9] = rad * rad;
        g[10] = 0.0f; g[11] = 0.0f;

        #pragma unroll
        for (int i = 0; i < 12; i++) sF[k * 12 + i] = F[k * 12 + i];
    }
    for (int idx = tid; idx < 15 * HH; idx += TPB) sW1[idx] = W1[idx];
    if (tid < HH) sB1[tid] = b1[tid];
    for (int idx = tid; idx < HH * CO; idx += TPB) sW2[idx] = W2[idx];
    if (tid < CO) sB2[tid] = b2[tid];
    __syncthreads();

    // ---------------- pass 1: sum + latent (thread = probe) ----------------
    const int n0 = blockIdx.x * TPB + tid;
    const int n = (n0 < N) ? n0 : (N - 1);
    const float px = pos[n * 3 + 0];
    const float py = pos[n * 3 + 1];
    const float pz = pos[n * 3 + 2];

    const float4* G4 = reinterpret_cast<const float4*>(sG);
    const float4* F4 = reinterpret_cast<const float4*>(sF);

    float lat[12];
    #pragma unroll
    for (int i = 0; i < 12; i++) lat[i] = 0.0f;
    float sum = 0.0f;

    #pragma unroll 4
    for (int k = 0; k < KG; k++) {
        float4 g0 = G4[3 * k + 0];
        float4 g1 = G4[3 * k + 1];
        float4 g2 = G4[3 * k + 2];
        float gv = gauss_eval(px, py, pz, g0, g1, g2);
        sum += gv;
        float4 f0 = F4[3 * k + 0];
        float4 f1 = F4[3 * k + 1];
        float4 f2 = F4[3 * k + 2];
        lat[0]  = fmaf(gv, f0.x, lat[0]);
        lat[1]  = fmaf(gv, f0.y, lat[1]);
        lat[2]  = fmaf(gv, f0.z, lat[2]);
        lat[3]  = fmaf(gv, f0.w, lat[3]);
        lat[4]  = fmaf(gv, f1.x, lat[4]);
        lat[5]  = fmaf(gv, f1.y, lat[5]);
        lat[6]  = fmaf(gv, f1.z, lat[6]);
        lat[7]  = fmaf(gv, f1.w, lat[7]);
        lat[8]  = fmaf(gv, f2.x, lat[8]);
        lat[9]  = fmaf(gv, f2.y, lat[9]);
        lat[10] = fmaf(gv, f2.z, lat[10]);
        lat[11] = fmaf(gv, f2.w, lat[11]);
    }

    const float inv = 1.0f / (sum + EPSF);
    #pragma unroll
    for (int i = 0; i < 12; i++) lat[i] *= inv;

    if (n0 < N) {
        float4* L = reinterpret_cast<float4*>(out_lat + (size_t)n0 * DF);
        L[0] = make_float4(lat[0], lat[1], lat[2], lat[3]);
        L[1] = make_float4(lat[4], lat[5], lat[6], lat[7]);
        L[2] = make_float4(lat[8], lat[9], lat[10], lat[11]);
    }

    // ---------------- MLP ----------------
    {
        float sh[CO];
        #pragma unroll
        for (int c = 0; c < CO; c++) sh[c] = sB2[c];
        #pragma unroll 4
        for (int j = 0; j < HH; j++) {
            float hj = sB1[j];
            #pragma unroll
            for (int i = 0; i < 12; i++) hj = fmaf(lat[i], sW1[i * HH + j], hj);
            hj = fmaf(px, sW1[12 * HH + j], hj);
            hj = fmaf(py, sW1[13 * HH + j], hj);
            hj = fmaf(pz, sW1[14 * HH + j], hj);
            hj = fmaxf(hj, 0.0f);
            #pragma unroll
            for (int c = 0; c < CO; c++) sh[c] = fmaf(hj, sW2[j * CO + c], sh[c]);
        }
        if (n0 < N) {
            float* S = out_sh + (size_t)n0 * CO;
            #pragma unroll
            for (int c = 0; c < CO; c++) S[c] = sh[c];
        }
    }

    // ---------------- pass 2: recompute gv, transpose, coalesced weights store ----------------
    {
        const int wid = tid >> 5;
        const int lane = tid & 31;
        float* tile = sT + wid * (32 * TLD);
        const int wbase = blockIdx.x * TPB + (wid << 5);

        for (int kc = 0; kc < KG; kc += 32) {
            #pragma unroll 4
            for (int kk = 0; kk < 32; kk++) {
                const int k = kc + kk;
                float4 g0 = G4[3 * k + 0];
                float4 g1 = G4[3 * k + 1];
                float4 g2 = G4[3 * k + 2];
                float gv = gauss_eval(px, py, pz, g0, g1, g2);
                tile[kk * TLD + lane] = gv * inv;
            }
            __syncwarp();
            #pragma unroll 4
            for (int p = 0; p < 32; p++) {
                const int np = wbase + p;
                if (np < N)
                    out_w[(size_t)np * KG + kc + lane] = tile[lane * TLD + p];
            }
            __syncwarp();
        }
    }
}

extern "C" void kernel_launch(void* const* d_in, const int* in_sizes, int n_in,
                              void* d_out, int out_size) {
    const float* pos   = (const float*)d_in[0];
    const float* mu    = (const float*)d_in[1];
    const float* log_s = (const float*)d_in[2];
    const float* q     = (const float*)d_in[3];
    const float* F     = (const float*)d_in[4];
    const float* W1    = (const float*)d_in[5];
    const float* b1    = (const float*)d_in[6];
    const float* W2    = (const float*)d_in[7];
    const float* b2    = (const float*)d_in[8];

    const int N = in_sizes[0] / 3;

    float* out = (float*)d_out;
    float* out_sh  = out;
    float* out_lat = out + (size_t)N * CO;
    float* out_w   = out + (size_t)N * (CO + DF);

    cudaFuncSetAttribute(gpc_kernel, cudaFuncAttributeMaxDynamicSharedMemorySize, SMEM_BYTES);

    const int grid = (N + TPB - 1) / TPB;
    gpc_kernel<<<grid, TPB, SMEM_BYTES>>>(pos, mu, log_s, q, F, W1, b1, W2, b2,
                                          out_sh, out_lat, out_w, N);
}

// round 3
// speedup vs baseline: 1.0260x; 1.0260x over previous
#include <cuda_runtime.h>
#include <cstddef>

#define KG   256
#define DF   12
#define CO   9
#define HH   32
#define EPSF 1e-8f

#define TPB  256          // threads per block; each thread handles 2 probes
#define PPB  (TPB * 2)    // probes per block

// ---- shared memory layout (floats), all params duplicated {v,v} for f32x2 ----
#define OFF_G   0                         // KG * 20 : {-mu0}x2,{-mu1}x2,{-mu2}x2,{cP00}x2,{cP11}x2,{cP22}x2,{2cP01}x2,{2cP02}x2,{2cP12}x2,{r2}x2
#define OFF_F   (OFF_G + KG * 20)         // KG * 24 : F[k][i] duplicated
#define OFF_W1  (OFF_F + KG * 24)         // 32 rows * 32 : W1d[j][2i(+1)] = W1[i][j], i<15, i=15 pad 0
#define OFF_B1  (OFF_W1 + 32 * 32)        // 64 : b1 dup
#define OFF_W2  (OFF_B1 + 64)             // 32 rows * 20 : W2d[j][2c(+1)] = W2[j][c], c<9, pad
#define OFF_B2  (OFF_W2 + 32 * 20)        // 12
#define SMEM_FLOATS (OFF_B2 + 12)
#define SMEM_BYTES  (SMEM_FLOATS * 4)

typedef unsigned long long u64;

union F4U { float4 v; u64 d[2]; };

__device__ __forceinline__ u64 pk(float lo, float hi) {
    u64 r; asm("mov.b64 %0, {%1, %2};" : "=l"(r) : "f"(lo), "f"(hi)); return r;
}
__device__ __forceinline__ void upk(u64 v, float& lo, float& hi) {
    asm("mov.b64 {%0, %1}, %2;" : "=f"(lo), "=f"(hi) : "l"(v));
}
__device__ __forceinline__ u64 addx(u64 a, u64 b) {
    u64 r; asm("add.rn.f32x2 %0, %1, %2;" : "=l"(r) : "l"(a), "l"(b)); return r;
}
__device__ __forceinline__ u64 mulx(u64 a, u64 b) {
    u64 r; asm("mul.rn.f32x2 %0, %1, %2;" : "=l"(r) : "l"(a), "l"(b)); return r;
}
__device__ __forceinline__ u64 fmx(u64 a, u64 b, u64 c) {
    u64 r; asm("fma.rn.f32x2 %0, %1, %2, %3;" : "=l"(r) : "l"(a), "l"(b), "l"(c)); return r;
}
__device__ __forceinline__ float ex2f(float x) {
    float r; asm("ex2.approx.ftz.f32 %0, %1;" : "=f"(r) : "f"(x)); return r;
}

// packed gaussian eval for 2 probes; returns {gv0, gv1}
__device__ __forceinline__ u64 gauss2(u64 px2, u64 py2, u64 pz2,
                                      F4U ga, F4U gb, F4U gc, F4U gd, F4U ge) {
    u64 d0 = addx(px2, ga.d[0]);
    u64 d1 = addx(py2, ga.d[1]);
    u64 d2 = addx(pz2, gb.d[0]);
    u64 aa = mulx(d0, d0);
    u64 bb = mulx(d1, d1);
    u64 cc = mulx(d2, d2);
    u64 dist2 = addx(addx(aa, bb), cc);
    u64 m = mulx(aa, gb.d[1]);
    m = fmx(bb, gc.d[0], m);
    m = fmx(cc, gc.d[1], m);
    m = fmx(mulx(d0, d1), gd.d[0], m);
    m = fmx(mulx(d0, d2), gd.d[1], m);
    m = fmx(mulx(d1, d2), ge.d[0], m);
    float m0, m1, q0, q1;
    upk(m, m0, m1);
    upk(dist2, q0, q1);
    const float r2 = ge.v.z;
    // masked: outside radius -> exponent -88 -> ex2 ~ 3e-27 (negligible vs ref's exact 0)
    m0 = (q0 < r2) ? m0 : -88.0f;
    m1 = (q1 < r2) ? m1 : -88.0f;
    return pk(ex2f(m0), ex2f(m1));
}

__global__ __launch_bounds__(TPB, 2)
void gpc_kernel(const float* __restrict__ pos,
                const float* __restrict__ mu,
                const float* __restrict__ log_s,
                const float* __restrict__ q,
                const float* __restrict__ F,
                const float* __restrict__ W1,
                const float* __restrict__ b1,
                const float* __restrict__ W2,
                const float* __restrict__ b2,
                float* __restrict__ out_sh,
                float* __restrict__ out_lat,
                float* __restrict__ out_w,
                int N) {
    extern __shared__ float sm[];
    float* sG  = sm + OFF_G;
    float* sF  = sm + OFF_F;
    float* sW1 = sm + OFF_W1;
    float* sB1 = sm + OFF_B1;
    float* sW2 = sm + OFF_W2;
    float* sB2 = sm + OFF_B2;

    const int tid = threadIdx.x;

    // -------- setup: one gaussian per thread, write duplicated params --------
    {
        const int k = tid;
        float m0 = mu[k * 3 + 0], m1 = mu[k * 3 + 1], m2 = mu[k * 3 + 2];

        float s0 = expf(log_s[k * 3 + 0]);
        float s1 = expf(log_s[k * 3 + 1]);
        float s2 = expf(log_s[k * 3 + 2]);
        float si0 = 1.0f / (s0 * s0 + EPSF);
        float si1 = 1.0f / (s1 * s1 + EPSF);
        float si2 = 1.0f / (s2 * s2 + EPSF);

        float qw = q[k * 4 + 0], qx = q[k * 4 + 1], qy = q[k * 4 + 2], qz = q[k * 4 + 3];
        float qn = sqrtf(qw * qw + qx * qx + qy * qy + qz * qz) + EPSF;
        qw /= qn; qx /= qn; qy /= qn; qz /= qn;

        float r00 = 1.0f - 2.0f * (qy * qy + qz * qz);
        float r01 = 2.0f * (qx * qy - qw * qz);
        float r02 = 2.0f * (qx * qz + qw * qy);
        float r10 = 2.0f * (qx * qy + qw * qz);
        float r11 = 1.0f - 2.0f * (qx * qx + qz * qz);
        float r12 = 2.0f * (qy * qz - qw * qx);
        float r20 = 2.0f * (qx * qz - qw * qy);
        float r21 = 2.0f * (qy * qz + qw * qx);
        float r22 = 1.0f - 2.0f * (qx * qx + qy * qy);

        float P00 = si0 * r00 * r00 + si1 * r01 * r01 + si2 * r02 * r02;
        float P11 = si0 * r10 * r10 + si1 * r11 * r11 + si2 * r12 * r12;
        float P22 = si0 * r20 * r20 + si1 * r21 * r21 + si2 * r22 * r22;
        float P01 = si0 * r00 * r10 + si1 * r01 * r11 + si2 * r02 * r12;
        float P02 = si0 * r00 * r20 + si1 * r01 * r21 + si2 * r02 * r22;
        float P12 = si0 * r10 * r20 + si1 * r11 * r21 + si2 * r12 * r22;

        const float cc = -0.72134752044448170f;  // -0.5 * log2(e)
        float smax = fmaxf(s0, fmaxf(s1, s2));
        float rad2 = 9.0f * smax * smax;

        float* g = sG + k * 20;
        g[0] = g[1] = -m0;
        g[2] = g[3] = -m1;
        g[4] = g[5] = -m2;
        g[6] = g[7] = cc * P00;
        g[8] = g[9] = cc * P11;
        g[10] = g[11] = cc * P22;
        g[12] = g[13] = 2.0f * cc * P01;
        g[14] = g[15] = 2.0f * cc * P02;
        g[16] = g[17] = 2.0f * cc * P12;
        g[18] = g[19] = rad2;

        float* f = sF + k * 24;
        #pragma unroll
        for (int i = 0; i < 12; i++) { float v = F[k * 12 + i]; f[2 * i] = v; f[2 * i + 1] = v; }
    }
    // W1 dup: sW1[j*32 + 2i(+1)] = W1[i*HH + j], i in [0,15), pad i=15 with 0
    for (int idx = tid; idx < 16 * 32; idx += TPB) {
        int j = idx & 31, i = idx >> 5;
        float v = (i < 15) ? W1[i * HH + j] : 0.0f;
        sW1[j * 32 + 2 * i] = v;
        sW1[j * 32 + 2 * i + 1] = v;
    }
    if (tid < HH) { float v = b1[tid]; sB1[2 * tid] = v; sB1[2 * tid + 1] = v; }
    // W2 dup: sW2[j*20 + 2c(+1)] = W2[j*CO + c], c<9, pad c=9 with 0
    for (int idx = tid; idx < 32 * 10; idx += TPB) {
        int j = idx / 10, c = idx % 10;
        float v = (c < 9) ? W2[j * CO + c] : 0.0f;
        sW2[j * 20 + 2 * c] = v;
        sW2[j * 20 + 2 * c + 1] = v;
    }
    if (tid < CO) sB2[tid] = b2[tid];
    __syncthreads();

    // -------- probe pair --------
    const int p0 = blockIdx.x * PPB + tid;
    const int p1 = p0 + TPB;
    const bool v0 = p0 < N;
    const bool v1 = p1 < N;
    const int n0 = v0 ? p0 : (N - 1);
    const int n1 = v1 ? p1 : (N - 1);

    const u64 px2 = pk(pos[n0 * 3 + 0], pos[n1 * 3 + 0]);
    const u64 py2 = pk(pos[n0 * 3 + 1], pos[n1 * 3 + 1]);
    const u64 pz2 = pk(pos[n0 * 3 + 2], pos[n1 * 3 + 2]);

    const F4U* G4 = reinterpret_cast<const F4U*>(sG);
    const F4U* F4 = reinterpret_cast<const F4U*>(sF);

    // -------- pass 1: sum + latent --------
    u64 lat[12];
    #pragma unroll
    for (int i = 0; i < 12; i++) lat[i] = 0ULL;
    u64 sum2 = 0ULL;

    #pragma unroll 8
    for (int k = 0; k < KG; k++) {
        F4U ga = G4[5 * k + 0], gb = G4[5 * k + 1], gc = G4[5 * k + 2],
            gd = G4[5 * k + 3], ge = G4[5 * k + 4];
        u64 gv = gauss2(px2, py2, pz2, ga, gb, gc, gd, ge);
        sum2 = addx(sum2, gv);
        F4U fa = F4[6 * k + 0], fb = F4[6 * k + 1], fc = F4[6 * k + 2],
            fd = F4[6 * k + 3], fe = F4[6 * k + 4], ff = F4[6 * k + 5];
        lat[0]  = fmx(gv, fa.d[0], lat[0]);
        lat[1]  = fmx(gv, fa.d[1], lat[1]);
        lat[2]  = fmx(gv, fb.d[0], lat[2]);
        lat[3]  = fmx(gv, fb.d[1], lat[3]);
        lat[4]  = fmx(gv, fc.d[0], lat[4]);
        lat[5]  = fmx(gv, fc.d[1], lat[5]);
        lat[6]  = fmx(gv, fd.d[0], lat[6]);
        lat[7]  = fmx(gv, fd.d[1], lat[7]);
        lat[8]  = fmx(gv, fe.d[0], lat[8]);
        lat[9]  = fmx(gv, fe.d[1], lat[9]);
        lat[10] = fmx(gv, ff.d[0], lat[10]);
        lat[11] = fmx(gv, ff.d[1], lat[11]);
    }

    float s0, s1;
    upk(sum2, s0, s1);
    const float inv0 = 1.0f / (s0 + EPSF);
    const float inv1 = 1.0f / (s1 + EPSF);
    const u64 inv2 = pk(inv0, inv1);

    #pragma unroll
    for (int i = 0; i < 12; i++) lat[i] = mulx(lat[i], inv2);

    // store latent
    {
        float a[12], b[12];
        #pragma unroll
        for (int i = 0; i < 12; i++) upk(lat[i], a[i], b[i]);
        if (v0) {
            float4* L = reinterpret_cast<float4*>(out_lat + (size_t)p0 * DF);
            L[0] = make_float4(a[0], a[1], a[2], a[3]);
            L[1] = make_float4(a[4], a[5], a[6], a[7]);
            L[2] = make_float4(a[8], a[9], a[10], a[11]);
        }
        if (v1) {
            float4* L = reinterpret_cast<float4*>(out_lat + (size_t)p1 * DF);
            L[0] = make_float4(b[0], b[1], b[2], b[3]);
            L[1] = make_float4(b[4], b[5], b[6], b[7]);
            L[2] = make_float4(b[8], b[9], b[10], b[11]);
        }
    }

    // -------- MLP (packed over the probe pair) --------
    {
        u64 in2[16];
        #pragma unroll
        for (int i = 0; i < 12; i++) in2[i] = lat[i];
        in2[12] = px2; in2[13] = py2; in2[14] = pz2; in2[15] = 0ULL;

        u64 sh2[CO];
        #pragma unroll
        for (int c = 0; c < CO; c++) { float bv = sB2[c]; sh2[c] = pk(bv, bv); }

        const u64* B1d = reinterpret_cast<const u64*>(sB1);
        #pragma unroll 4
        for (int j = 0; j < HH; j++) {
            u64 h2 = B1d[j];
            const F4U* w1r = reinterpret_cast<const F4U*>(sW1 + j * 32);
            #pragma unroll
            for (int i2 = 0; i2 < 8; i2++) {
                F4U w = w1r[i2];
                h2 = fmx(in2[2 * i2 + 0], w.d[0], h2);
                h2 = fmx(in2[2 * i2 + 1], w.d[1], h2);
            }
            float h0, h1;
            upk(h2, h0, h1);
            h2 = pk(fmaxf(h0, 0.0f), fmaxf(h1, 0.0f));
            const F4U* w2r = reinterpret_cast<const F4U*>(sW2 + j * 20);
            F4U w20 = w2r[0], w21 = w2r[1], w22 = w2r[2], w23 = w2r[3], w24 = w2r[4];
            sh2[0] = fmx(h2, w20.d[0], sh2[0]);
            sh2[1] = fmx(h2, w20.d[1], sh2[1]);
            sh2[2] = fmx(h2, w21.d[0], sh2[2]);
            sh2[3] = fmx(h2, w21.d[1], sh2[3]);
            sh2[4] = fmx(h2, w22.d[0], sh2[4]);
            sh2[5] = fmx(h2, w22.d[1], sh2[5]);
            sh2[6] = fmx(h2, w23.d[0], sh2[6]);
            sh2[7] = fmx(h2, w23.d[1], sh2[7]);
            sh2[8] = fmx(h2, w24.d[0], sh2[8]);
        }
        float sa[CO], sb[CO];
        #pragma unroll
        for (int c = 0; c < CO; c++) upk(sh2[c], sa[c], sb[c]);
        if (v0) {
            float* S = out_sh + (size_t)p0 * CO;
            #pragma unroll
            for (int c = 0; c < CO; c++) S[c] = sa[c];
        }
        if (v1) {
            float* S = out_sh + (size_t)p1 * CO;
            #pragma unroll
            for (int c = 0; c < CO; c++) S[c] = sb[c];
        }
    }

    // -------- pass 2: recompute gv, normalized weights, direct coalesced-ish stores --------
    {
        float* row0 = out_w + (size_t)p0 * KG;
        float* row1 = out_w + (size_t)p1 * KG;

        for (int kc = 0; kc < KG; kc += 8) {
            float w0[8], w1[8];
            #pragma unroll
            for (int kk = 0; kk < 8; kk++) {
                const int k = kc + kk;
                F4U ga = G4[5 * k + 0], gb = G4[5 * k + 1], gc = G4[5 * k + 2],
                    gd = G4[5 * k + 3], ge = G4[5 * k + 4];
                u64 gv = mulx(gauss2(px2, py2, pz2, ga, gb, gc, gd, ge), inv2);
                upk(gv, w0[kk], w1[kk]);
            }
            if (v0) {
                float4* R = reinterpret_cast<float4*>(row0 + kc);
                R[0] = make_float4(w0[0], w0[1], w0[2], w0[3]);
                R[1] = make_float4(w0[4], w0[5], w0[6], w0[7]);
            }
            if (v1) {
                float4* R = reinterpret_cast<float4*>(row1 + kc);
                R[0] = make_float4(w1[0], w1[1], w1[2], w1[3]);
                R[1] = make_float4(w1[4], w1[5], w1[6], w1[7]);
            }
        }
    }
}

extern "C" void kernel_launch(void* const* d_in, const int* in_sizes, int n_in,
                              void* d_out, int out_size) {
    const float* pos   = (const float*)d_in[0];
    const float* mu    = (const float*)d_in[1];
    const float* log_s = (const float*)d_in[2];
    const float* q     = (const float*)d_in[3];
    const float* F     = (const float*)d_in[4];
    const float* W1    = (const float*)d_in[5];
    const float* b1    = (const float*)d_in[6];
    const float* W2    = (const float*)d_in[7];
    const float* b2    = (const float*)d_in[8];

    const int N = in_sizes[0] / 3;

    float* out = (float*)d_out;
    float* out_sh  = out;
    float* out_lat = out + (size_t)N * CO;
    float* out_w   = out + (size_t)N * (CO + DF);

    cudaFuncSetAttribute(gpc_kernel, cudaFuncAttributeMaxDynamicSharedMemorySize, SMEM_BYTES);

    const int grid = (N + PPB - 1) / PPB;
    gpc_kernel<<<grid, TPB, SMEM_BYTES>>>(pos, mu, log_s, q, F, W1, b1, W2, b2,
                                          out_sh, out_lat, out_w, N);
}

// round 4
// speedup vs baseline: 1.0265x; 1.0006x over previous
#include <cuda_runtime.h>
#include <cstddef>

#define KG   256
#define DF   12
#define CO   9
#define HH   32
#define EPSF 1e-8f

#define TPB  256          // threads per block; each thread handles 2 probes
#define PPB  (TPB * 2)    // probes per block

// ---- shared memory layout (floats), all params duplicated {v,v} for f32x2 ----
#define OFF_G   0                         // KG * 20 : {-mu0}x2,{-mu1}x2,{-mu2}x2,{cP00}x2,{cP11}x2,{cP22}x2,{2cP01}x2,{2cP02}x2,{2cP12}x2,{r2}x2
#define OFF_F   (OFF_G + KG * 20)         // KG * 24 : F[k][i] duplicated
#define OFF_W1  (OFF_F + KG * 24)         // 32 rows * 32 : W1d[j][2i(+1)] = W1[i][j], i<15, i=15 pad 0
#define OFF_B1  (OFF_W1 + 32 * 32)        // 64 : b1 dup
#define OFF_W2  (OFF_B1 + 64)             // 32 rows * 20 : W2d[j][2c(+1)] = W2[j][c], c<9, pad
#define OFF_B2  (OFF_W2 + 32 * 20)        // 12
#define SMEM_FLOATS (OFF_B2 + 12)
#define SMEM_BYTES  (SMEM_FLOATS * 4)

typedef unsigned long long u64;

union F4U { float4 v; u64 d[2]; };

__device__ __forceinline__ u64 pk(float lo, float hi) {
    u64 r; asm("mov.b64 %0, {%1, %2};" : "=l"(r) : "f"(lo), "f"(hi)); return r;
}
__device__ __forceinline__ void upk(u64 v, float& lo, float& hi) {
    asm("mov.b64 {%0, %1}, %2;" : "=f"(lo), "=f"(hi) : "l"(v));
}
__device__ __forceinline__ u64 addx(u64 a, u64 b) {
    u64 r; asm("add.rn.f32x2 %0, %1, %2;" : "=l"(r) : "l"(a), "l"(b)); return r;
}
__device__ __forceinline__ u64 mulx(u64 a, u64 b) {
    u64 r; asm("mul.rn.f32x2 %0, %1, %2;" : "=l"(r) : "l"(a), "l"(b)); return r;
}
__device__ __forceinline__ u64 fmx(u64 a, u64 b, u64 c) {
    u64 r; asm("fma.rn.f32x2 %0, %1, %2, %3;" : "=l"(r) : "l"(a), "l"(b), "l"(c)); return r;
}
__device__ __forceinline__ float ex2f(float x) {
    float r; asm("ex2.approx.ftz.f32 %0, %1;" : "=f"(r) : "f"(x)); return r;
}

// packed gaussian eval for 2 probes; returns {gv0, gv1}
__device__ __forceinline__ u64 gauss2(u64 px2, u64 py2, u64 pz2,
                                      F4U ga, F4U gb, F4U gc, F4U gd, F4U ge) {
    u64 d0 = addx(px2, ga.d[0]);
    u64 d1 = addx(py2, ga.d[1]);
    u64 d2 = addx(pz2, gb.d[0]);
    u64 aa = mulx(d0, d0);
    u64 bb = mulx(d1, d1);
    u64 cc = mulx(d2, d2);
    u64 dist2 = addx(addx(aa, bb), cc);
    u64 m = mulx(aa, gb.d[1]);
    m = fmx(bb, gc.d[0], m);
    m = fmx(cc, gc.d[1], m);
    m = fmx(mulx(d0, d1), gd.d[0], m);
    m = fmx(mulx(d0, d2), gd.d[1], m);
    m = fmx(mulx(d1, d2), ge.d[0], m);
    float m0, m1, q0, q1;
    upk(m, m0, m1);
    upk(dist2, q0, q1);
    const float r2 = ge.v.z;
    // masked: outside radius -> exponent -88 -> ex2 ~ 3e-27 (negligible vs ref's exact 0)
    m0 = (q0 < r2) ? m0 : -88.0f;
    m1 = (q1 < r2) ? m1 : -88.0f;
    return pk(ex2f(m0), ex2f(m1));
}

__global__ __launch_bounds__(TPB, 2)
void gpc_kernel(const float* __restrict__ pos,
                const float* __restrict__ mu,
                const float* __restrict__ log_s,
                const float* __restrict__ q,
                const float* __restrict__ F,
                const float* __restrict__ W1,
                const float* __restrict__ b1,
                const float* __restrict__ W2,
                const float* __restrict__ b2,
                float* __restrict__ out_sh,
                float* __restrict__ out_lat,
                float* __restrict__ out_w,
                int N) {
    extern __shared__ float sm[];
    float* sG  = sm + OFF_G;
    float* sF  = sm + OFF_F;
    float* sW1 = sm + OFF_W1;
    float* sB1 = sm + OFF_B1;
    float* sW2 = sm + OFF_W2;
    float* sB2 = sm + OFF_B2;

    const int tid = threadIdx.x;

    // -------- setup: one gaussian per thread, write duplicated params --------
    {
        const int k = tid;
        float m0 = mu[k * 3 + 0], m1 = mu[k * 3 + 1], m2 = mu[k * 3 + 2];

        float s0 = expf(log_s[k * 3 + 0]);
        float s1 = expf(log_s[k * 3 + 1]);
        float s2 = expf(log_s[k * 3 + 2]);
        float si0 = 1.0f / (s0 * s0 + EPSF);
        float si1 = 1.0f / (s1 * s1 + EPSF);
        float si2 = 1.0f / (s2 * s2 + EPSF);

        float qw = q[k * 4 + 0], qx = q[k * 4 + 1], qy = q[k * 4 + 2], qz = q[k * 4 + 3];
        float qn = sqrtf(qw * qw + qx * qx + qy * qy + qz * qz) + EPSF;
        qw /= qn; qx /= qn; qy /= qn; qz /= qn;

        float r00 = 1.0f - 2.0f * (qy * qy + qz * qz);
        float r01 = 2.0f * (qx * qy - qw * qz);
        float r02 = 2.0f * (qx * qz + qw * qy);
        float r10 = 2.0f * (qx * qy + qw * qz);
        float r11 = 1.0f - 2.0f * (qx * qx + qz * qz);
        float r12 = 2.0f * (qy * qz - qw * qx);
        float r20 = 2.0f * (qx * qz - qw * qy);
        float r21 = 2.0f * (qy * qz + qw * qx);
        float r22 = 1.0f - 2.0f * (qx * qx + qy * qy);

        float P00 = si0 * r00 * r00 + si1 * r01 * r01 + si2 * r02 * r02;
        float P11 = si0 * r10 * r10 + si1 * r11 * r11 + si2 * r12 * r12;
        float P22 = si0 * r20 * r20 + si1 * r21 * r21 + si2 * r22 * r22;
        float P01 = si0 * r00 * r10 + si1 * r01 * r11 + si2 * r02 * r12;
        float P02 = si0 * r00 * r20 + si1 * r01 * r21 + si2 * r02 * r22;
        float P12 = si0 * r10 * r20 + si1 * r11 * r21 + si2 * r12 * r22;

        const float cc = -0.72134752044448170f;  // -0.5 * log2(e)
        float smax = fmaxf(s0, fmaxf(s1, s2));
        float rad2 = 9.0f * smax * smax;

        float* g = sG + k * 20;
        g[0] = g[1] = -m0;
        g[2] = g[3] = -m1;
        g[4] = g[5] = -m2;
        g[6] = g[7] = cc * P00;
        g[8] = g[9] = cc * P11;
        g[10] = g[11] = cc * P22;
        g[12] = g[13] = 2.0f * cc * P01;
        g[14] = g[15] = 2.0f * cc * P02;
        g[16] = g[17] = 2.0f * cc * P12;
        g[18] = g[19] = rad2;

        float* f = sF + k * 24;
        #pragma unroll
        for (int i = 0; i < 12; i++) { float v = F[k * 12 + i]; f[2 * i] = v; f[2 * i + 1] = v; }
    }
    // W1 dup: sW1[j*32 + 2i(+1)] = W1[i*HH + j], i in [0,15), pad i=15 with 0
    for (int idx = tid; idx < 16 * 32; idx += TPB) {
        int j = idx & 31, i = idx >> 5;
        float v = (i < 15) ? W1[i * HH + j] : 0.0f;
        sW1[j * 32 + 2 * i] = v;
        sW1[j * 32 + 2 * i + 1] = v;
    }
    if (tid < HH) { float v = b1[tid]; sB1[2 * tid] = v; sB1[2 * tid + 1] = v; }
    // W2 dup: sW2[j*20 + 2c(+1)] = W2[j*CO + c], c<9, pad c=9 with 0
    for (int idx = tid; idx < 32 * 10; idx += TPB) {
        int j = idx / 10, c = idx % 10;
        float v = (c < 9) ? W2[j * CO + c] : 0.0f;
        sW2[j * 20 + 2 * c] = v;
        sW2[j * 20 + 2 * c + 1] = v;
    }
    if (tid < CO) sB2[tid] = b2[tid];
    __syncthreads();

    // -------- probe pair --------
    const int p0 = blockIdx.x * PPB + tid;
    const int p1 = p0 + TPB;
    const bool v0 = p0 < N;
    const bool v1 = p1 < N;
    const int n0 = v0 ? p0 : (N - 1);
    const int n1 = v1 ? p1 : (N - 1);

    const u64 px2 = pk(pos[n0 * 3 + 0], pos[n1 * 3 + 0]);
    const u64 py2 = pk(pos[n0 * 3 + 1], pos[n1 * 3 + 1]);
    const u64 pz2 = pk(pos[n0 * 3 + 2], pos[n1 * 3 + 2]);

    const F4U* G4 = reinterpret_cast<const F4U*>(sG);
    const F4U* F4 = reinterpret_cast<const F4U*>(sF);

    // -------- pass 1: sum + latent --------
    u64 lat[12];
    #pragma unroll
    for (int i = 0; i < 12; i++) lat[i] = 0ULL;
    u64 sum2 = 0ULL;

    #pragma unroll 8
    for (int k = 0; k < KG; k++) {
        F4U ga = G4[5 * k + 0], gb = G4[5 * k + 1], gc = G4[5 * k + 2],
            gd = G4[5 * k + 3], ge = G4[5 * k + 4];
        u64 gv = gauss2(px2, py2, pz2, ga, gb, gc, gd, ge);
        sum2 = addx(sum2, gv);
        F4U fa = F4[6 * k + 0], fb = F4[6 * k + 1], fc = F4[6 * k + 2],
            fd = F4[6 * k + 3], fe = F4[6 * k + 4], ff = F4[6 * k + 5];
        lat[0]  = fmx(gv, fa.d[0], lat[0]);
        lat[1]  = fmx(gv, fa.d[1], lat[1]);
        lat[2]  = fmx(gv, fb.d[0], lat[2]);
        lat[3]  = fmx(gv, fb.d[1], lat[3]);
        lat[4]  = fmx(gv, fc.d[0], lat[4]);
        lat[5]  = fmx(gv, fc.d[1], lat[5]);
        lat[6]  = fmx(gv, fd.d[0], lat[6]);
        lat[7]  = fmx(gv, fd.d[1], lat[7]);
        lat[8]  = fmx(gv, fe.d[0], lat[8]);
        lat[9]  = fmx(gv, fe.d[1], lat[9]);
        lat[10] = fmx(gv, ff.d[0], lat[10]);
        lat[11] = fmx(gv, ff.d[1], lat[11]);
    }

    float s0, s1;
    upk(sum2, s0, s1);
    const float inv0 = 1.0f / (s0 + EPSF);
    const float inv1 = 1.0f / (s1 + EPSF);
    const u64 inv2 = pk(inv0, inv1);

    #pragma unroll
    for (int i = 0; i < 12; i++) lat[i] = mulx(lat[i], inv2);

    // store latent
    {
        float a[12], b[12];
        #pragma unroll
        for (int i = 0; i < 12; i++) upk(lat[i], a[i], b[i]);
        if (v0) {
            float4* L = reinterpret_cast<float4*>(out_lat + (size_t)p0 * DF);
            L[0] = make_float4(a[0], a[1], a[2], a[3]);
            L[1] = make_float4(a[4], a[5], a[6], a[7]);
            L[2] = make_float4(a[8], a[9], a[10], a[11]);
        }
        if (v1) {
            float4* L = reinterpret_cast<float4*>(out_lat + (size_t)p1 * DF);
            L[0] = make_float4(b[0], b[1], b[2], b[3]);
            L[1] = make_float4(b[4], b[5], b[6], b[7]);
            L[2] = make_float4(b[8], b[9], b[10], b[11]);
        }
    }

    // -------- MLP (packed over the probe pair) --------
    {
        u64 in2[16];
        #pragma unroll
        for (int i = 0; i < 12; i++) in2[i] = lat[i];
        in2[12] = px2; in2[13] = py2; in2[14] = pz2; in2[15] = 0ULL;

        u64 sh2[CO];
        #pragma unroll
        for (int c = 0; c < CO; c++) { float bv = sB2[c]; sh2[c] = pk(bv, bv); }

        const u64* B1d = reinterpret_cast<const u64*>(sB1);
        #pragma unroll 4
        for (int j = 0; j < HH; j++) {
            u64 h2 = B1d[j];
            const F4U* w1r = reinterpret_cast<const F4U*>(sW1 + j * 32);
            #pragma unroll
            for (int i2 = 0; i2 < 8; i2++) {
                F4U w = w1r[i2];
                h2 = fmx(in2[2 * i2 + 0], w.d[0], h2);
                h2 = fmx(in2[2 * i2 + 1], w.d[1], h2);
            }
            float h0, h1;
            upk(h2, h0, h1);
            h2 = pk(fmaxf(h0, 0.0f), fmaxf(h1, 0.0f));
            const F4U* w2r = reinterpret_cast<const F4U*>(sW2 + j * 20);
            F4U w20 = w2r[0], w21 = w2r[1], w22 = w2r[2], w23 = w2r[3], w24 = w2r[4];
            sh2[0] = fmx(h2, w20.d[0], sh2[0]);
            sh2[1] = fmx(h2, w20.d[1], sh2[1]);
            sh2[2] = fmx(h2, w21.d[0], sh2[2]);
            sh2[3] = fmx(h2, w21.d[1], sh2[3]);
            sh2[4] = fmx(h2, w22.d[0], sh2[4]);
            sh2[5] = fmx(h2, w22.d[1], sh2[5]);
            sh2[6] = fmx(h2, w23.d[0], sh2[6]);
            sh2[7] = fmx(h2, w23.d[1], sh2[7]);
            sh2[8] = fmx(h2, w24.d[0], sh2[8]);
        }
        float sa[CO], sb[CO];
        #pragma unroll
        for (int c = 0; c < CO; c++) upk(sh2[c], sa[c], sb[c]);
        if (v0) {
            float* S = out_sh + (size_t)p0 * CO;
            #pragma unroll
            for (int c = 0; c < CO; c++) S[c] = sa[c];
        }
        if (v1) {
            float* S = out_sh + (size_t)p1 * CO;
            #pragma unroll
            for (int c = 0; c < CO; c++) S[c] = sb[c];
        }
    }

    // -------- pass 2: recompute gv, normalized weights, direct coalesced-ish stores --------
    {
        float* row0 = out_w + (size_t)p0 * KG;
        float* row1 = out_w + (size_t)p1 * KG;

        for (int kc = 0; kc < KG; kc += 8) {
            float w0[8], w1[8];
            #pragma unroll
            for (int kk = 0; kk < 8; kk++) {
                const int k = kc + kk;
                F4U ga = G4[5 * k + 0], gb = G4[5 * k + 1], gc = G4[5 * k + 2],
                    gd = G4[5 * k + 3], ge = G4[5 * k + 4];
                u64 gv = mulx(gauss2(px2, py2, pz2, ga, gb, gc, gd, ge), inv2);
                upk(gv, w0[kk], w1[kk]);
            }
            if (v0) {
                float4* R = reinterpret_cast<float4*>(row0 + kc);
                R[0] = make_float4(w0[0], w0[1], w0[2], w0[3]);
                R[1] = make_float4(w0[4], w0[5], w0[6], w0[7]);
            }
            if (v1) {
                float4* R = reinterpret_cast<float4*>(row1 + kc);
                R[0] = make_float4(w1[0], w1[1], w1[2], w1[3]);
                R[1] = make_float4(w1[4], w1[5], w1[6], w1[7]);
            }
        }
    }
}

extern "C" void kernel_launch(void* const* d_in, const int* in_sizes, int n_in,
                              void* d_out, int out_size) {
    const float* pos   = (const float*)d_in[0];
    const float* mu    = (const float*)d_in[1];
    const float* log_s = (const float*)d_in[2];
    const float* q     = (const float*)d_in[3];
    const float* F     = (const float*)d_in[4];
    const float* W1    = (const float*)d_in[5];
    const float* b1    = (const float*)d_in[6];
    const float* W2    = (const float*)d_in[7];
    const float* b2    = (const float*)d_in[8];

    const int N = in_sizes[0] / 3;

    float* out = (float*)d_out;
    float* out_sh  = out;
    float* out_lat = out + (size_t)N * CO;
    float* out_w   = out + (size_t)N * (CO + DF);

    cudaFuncSetAttribute(gpc_kernel, cudaFuncAttributeMaxDynamicSharedMemorySize, SMEM_BYTES);

    const int grid = (N + PPB - 1) / PPB;
    gpc_kernel<<<grid, TPB, SMEM_BYTES>>>(pos, mu, log_s, q, F, W1, b1, W2, b2,
                                          out_sh, out_lat, out_w, N);
}